// round 4
// baseline (speedup 1.0000x reference)
#include <cuda_runtime.h>
#include <cuda_bf16.h>
#include <math.h>

#define NN 50000
#define NE 800000
#define TT 12
#define NPB 64
#define SROW 68   // padded row stride for [64][n] shared tiles (16B-aligned)

// Scratch (static device globals: allocation-free at launch time).
__device__ float g_deg[NN];
__device__ float g_dinv[NN];
__device__ float g_agg[NN * 24];
__device__ int   g_is64;   // 1 if edge_index is int64, 0 if int32

// ---------------------------------------------------------------------------
__global__ void k_init() {
    int i = blockIdx.x * blockDim.x + threadIdx.x;
    int stride = gridDim.x * blockDim.x;
    for (int j = i; j < NN; j += stride) g_deg[j] = 0.0f;
    for (int j = i; j < NN * 24; j += stride) g_agg[j] = 0.0f;
}

// Detect edge_index element width. If int64 (values < 2^31, nonneg), the high
// 32-bit word of every element is 0. If int32, odd words are src indices —
// the odds of 1024 of them all being zero are ~0.
__global__ void k_probe(const int* __restrict__ ei32) {
    int nz = 0;
    for (int j = threadIdx.x; j < 1024; j += blockDim.x)
        if (ei32[2 * j + 1] != 0) nz = 1;
    int any = __syncthreads_or(nz);
    if (threadIdx.x == 0) g_is64 = any ? 0 : 1;
}

__device__ __forceinline__ void load_edge(const int* ei32, int e, int& s, int& d) {
    if (g_is64) {            // int64 layout: dword 2i = low word of element i
        s = ei32[2 * e];
        d = ei32[2 * (NE + e)];
    } else {                 // int32 layout
        s = ei32[e];
        d = ei32[NE + e];
    }
}

__global__ void k_deg(const int* __restrict__ ei32) {
    int e = blockIdx.x * blockDim.x + threadIdx.x;
    if (e >= NE) return;
    int s, d;
    load_edge(ei32, e, s, d);
    atomicAdd(&g_deg[d], 1.0f);
}

__global__ void k_dinv() {
    int n = blockIdx.x * blockDim.x + threadIdx.x;
    if (n < NN) g_dinv[n] = rsqrtf(g_deg[n] + 1.0f);
}

// Aggregate raw x over edges for all 12 timesteps & 2 channels at once:
// g_agg[dst][t][c] += dinv[src]*dinv[dst] * x[src][t][c]
__global__ void k_scatter(const int* __restrict__ ei32,
                          const float* __restrict__ x) {
    int e = blockIdx.x * blockDim.x + threadIdx.x;
    if (e >= NE) return;
    int s, d;
    load_edge(ei32, e, s, d);
    float w = g_dinv[s] * g_dinv[d];
    const float4* xs = (const float4*)(x + (size_t)s * 24);
    float* ag = g_agg + (size_t)d * 24;
#pragma unroll
    for (int q = 0; q < 6; q++) {
        float4 v = xs[q];
        atomicAdd(&ag[4 * q + 0], w * v.x);
        atomicAdd(&ag[4 * q + 1], w * v.y);
        atomicAdd(&ag[4 * q + 2], w * v.z);
        atomicAdd(&ag[4 * q + 3], w * v.w);
    }
}

// ---------------------------------------------------------------------------
// Fused: GCN projection (2->64) + 12-step GRU + FC readout, per node tile.
// Block: 256 threads = 4 (ty, 16 nodes each) x 64 (tx = gate column j).
// Hidden state lives in SMEM for the whole time loop.
__global__ void __launch_bounds__(256, 1)
k_fused(const float* __restrict__ x,
        const float* __restrict__ W_gcn, const float* __restrict__ b_gcn,
        const float* __restrict__ W_ih,  const float* __restrict__ W_hh,
        const float* __restrict__ b_ih,  const float* __restrict__ b_hh,
        const float* __restrict__ W_fc,  const float* __restrict__ b_fc,
        float* __restrict__ out) {
    extern __shared__ float sm[];
    float* sWih = sm;                 // [64][192] k-major (transposed)
    float* sWhh = sWih + 64 * 192;    // [64][192]
    float* sBih = sWhh + 64 * 192;    // 192
    float* sBhh = sBih + 192;         // 192
    float* sWg  = sBhh + 192;         // [2][64]
    float* sBg  = sWg + 128;          // 64
    float* sWfc = sBg + 64;           // 64
    float* sXA  = sWfc + 64;          // [NPB][24] : agg + self_norm*x
    float* sS   = sXA + NPB * 24;     // [64][SROW] spatial (k-major: [k][node])
    float* sH   = sS + 64 * SROW;     // [64][SROW] hidden (k-major)

    int tid = threadIdx.x;
    int node0 = blockIdx.x * NPB;

    // Load weights transposed (coalesced global read, scattered smem write)
    for (int i = tid; i < 192 * 64; i += 256) {
        int g = i >> 6, k = i & 63;
        sWih[k * 192 + g] = W_ih[i];
        sWhh[k * 192 + g] = W_hh[i];
    }
    for (int i = tid; i < 192; i += 256) { sBih[i] = b_ih[i]; sBhh[i] = b_hh[i]; }
    for (int i = tid; i < 128; i += 256) sWg[i] = W_gcn[i];
    if (tid < 64) { sBg[tid] = b_gcn[tid]; sWfc[tid] = W_fc[tid]; }

    // xagg[n][i] = agg[node][i] + self_norm[node]*x[node][i]
    for (int i = tid; i < NPB * 24; i += 256) {
        int n = i / 24, c = i - n * 24;
        int node = node0 + n;
        float v = 0.0f;
        if (node < NN) {
            float dv = g_dinv[node];
            v = g_agg[(size_t)node * 24 + c] + dv * dv * x[(size_t)node * 24 + c];
        }
        sXA[i] = v;
    }
    for (int i = tid; i < 64 * SROW; i += 256) sH[i] = 0.0f;
    __syncthreads();

    int tx = tid & 63;   // gate column j (0..63)
    int ty = tid >> 6;   // node-group (0..3)
    int nb = ty * 16;    // first node in this thread's tile

    float br  = sBih[tx]       + sBhh[tx];
    float bz  = sBih[64 + tx]  + sBhh[64 + tx];
    float bin = sBih[128 + tx];
    float bhn = sBhh[128 + tx];
    float wg0 = sWg[tx], wg1 = sWg[64 + tx], bg = sBg[tx];

    for (int t = 0; t < TT; t++) {
        // spatial s[j=tx][n] = relu(xa0*Wg0 + xa1*Wg1 + bg)
#pragma unroll
        for (int i = 0; i < 16; i++) {
            int n = nb + i;
            float a0 = sXA[n * 24 + 2 * t];
            float a1 = sXA[n * 24 + 2 * t + 1];
            float v = fmaf(a0, wg0, fmaf(a1, wg1, bg));
            sS[tx * SROW + n] = fmaxf(v, 0.0f);
        }
        __syncthreads();

        float ar[16], az[16], ain[16], ahn[16];
#pragma unroll
        for (int i = 0; i < 16; i++) { ar[i] = br; az[i] = bz; ain[i] = bin; ahn[i] = bhn; }

        // fused GEMMs: gi = s @ Wih^T (r,z,n) and gh = h @ Whh^T (r,z,n)
#pragma unroll 4
        for (int k = 0; k < 64; k++) {
            const float* wik = &sWih[k * 192 + tx];
            const float* whk = &sWhh[k * 192 + tx];
            float wr = wik[0], wz = wik[64], wn = wik[128];
            float vr = whk[0], vz = whk[64], vn = whk[128];
            const float4* sp = (const float4*)&sS[k * SROW + nb];
            const float4* hp = (const float4*)&sH[k * SROW + nb];
#pragma unroll
            for (int q = 0; q < 4; q++) {
                float4 sv = sp[q];
                float4 hv = hp[q];
                ar[4*q+0] = fmaf(sv.x, wr, ar[4*q+0]);
                ar[4*q+1] = fmaf(sv.y, wr, ar[4*q+1]);
                ar[4*q+2] = fmaf(sv.z, wr, ar[4*q+2]);
                ar[4*q+3] = fmaf(sv.w, wr, ar[4*q+3]);
                az[4*q+0] = fmaf(sv.x, wz, az[4*q+0]);
                az[4*q+1] = fmaf(sv.y, wz, az[4*q+1]);
                az[4*q+2] = fmaf(sv.z, wz, az[4*q+2]);
                az[4*q+3] = fmaf(sv.w, wz, az[4*q+3]);
                ain[4*q+0] = fmaf(sv.x, wn, ain[4*q+0]);
                ain[4*q+1] = fmaf(sv.y, wn, ain[4*q+1]);
                ain[4*q+2] = fmaf(sv.z, wn, ain[4*q+2]);
                ain[4*q+3] = fmaf(sv.w, wn, ain[4*q+3]);
                ar[4*q+0] = fmaf(hv.x, vr, ar[4*q+0]);
                ar[4*q+1] = fmaf(hv.y, vr, ar[4*q+1]);
                ar[4*q+2] = fmaf(hv.z, vr, ar[4*q+2]);
                ar[4*q+3] = fmaf(hv.w, vr, ar[4*q+3]);
                az[4*q+0] = fmaf(hv.x, vz, az[4*q+0]);
                az[4*q+1] = fmaf(hv.y, vz, az[4*q+1]);
                az[4*q+2] = fmaf(hv.z, vz, az[4*q+2]);
                az[4*q+3] = fmaf(hv.w, vz, az[4*q+3]);
                ahn[4*q+0] = fmaf(hv.x, vn, ahn[4*q+0]);
                ahn[4*q+1] = fmaf(hv.y, vn, ahn[4*q+1]);
                ahn[4*q+2] = fmaf(hv.z, vn, ahn[4*q+2]);
                ahn[4*q+3] = fmaf(hv.w, vn, ahn[4*q+3]);
            }
        }
        __syncthreads();  // all reads of sH/sS complete

        // gates + hidden update (thread owns h[j=tx][nb..nb+15])
#pragma unroll
        for (int i = 0; i < 16; i++) {
            int n = nb + i;
            float r  = 1.0f / (1.0f + __expf(-ar[i]));
            float z  = 1.0f / (1.0f + __expf(-az[i]));
            float nn = tanhf(fmaf(r, ahn[i], ain[i]));
            float hold = sH[tx * SROW + n];
            sH[tx * SROW + n] = fmaf(z, hold - nn, nn);  // (1-z)*nn + z*h
        }
        __syncthreads();
    }

    // FC readout: out[n] = sum_j h[n][j] * W_fc[j] + b_fc
    if (tid < NPB) {
        int node = node0 + tid;
        if (node < NN) {
            float acc = b_fc[0];
#pragma unroll
            for (int j = 0; j < 64; j++)
                acc = fmaf(sH[j * SROW + tid], sWfc[j], acc);
            out[node] = acc;
        }
    }
}

// ---------------------------------------------------------------------------
extern "C" void kernel_launch(void* const* d_in, const int* in_sizes, int n_in,
                              void* d_out, int out_size) {
    const float* x     = (const float*)d_in[0];
    const int*   ei32  = (const int*)d_in[1];   // int32 OR int64 (probed on device)
    const float* W_gcn = (const float*)d_in[2];
    const float* b_gcn = (const float*)d_in[3];
    const float* W_ih  = (const float*)d_in[4];
    const float* W_hh  = (const float*)d_in[5];
    const float* b_ih  = (const float*)d_in[6];
    const float* b_hh  = (const float*)d_in[7];
    const float* W_fc  = (const float*)d_in[8];
    const float* b_fc  = (const float*)d_in[9];
    float* out = (float*)d_out;

    const int smem_bytes =
        (2 * 64 * 192 + 2 * 192 + 128 + 64 + 64 + NPB * 24 + 2 * 64 * SROW) * 4;

    static bool attr_set = false;
    if (!attr_set) {
        cudaFuncSetAttribute(k_fused, cudaFuncAttributeMaxDynamicSharedMemorySize,
                             smem_bytes);
        attr_set = true;
    }

    k_init<<<256, 256>>>();
    k_probe<<<1, 256>>>(ei32);
    k_deg<<<(NE + 255) / 256, 256>>>(ei32);
    k_dinv<<<(NN + 255) / 256, 256>>>();
    k_scatter<<<(NE + 255) / 256, 256>>>(ei32, x);
    k_fused<<<(NN + NPB - 1) / NPB, 256, smem_bytes>>>(
        x, W_gcn, b_gcn, W_ih, W_hh, b_ih, b_hh, W_fc, b_fc, out);
}

// round 5
// speedup vs baseline: 1.0181x; 1.0181x over previous
#include <cuda_runtime.h>
#include <cuda_bf16.h>
#include <math.h>

#define NN 50000
#define NE 800000
#define TT 12
#define NPB 64
#define SROW 68   // padded row stride for [64][n] shared tiles (16B-aligned)

// Scratch (static device globals: allocation-free at launch time).
__device__ float g_deg[NN];
__device__ float g_dinv[NN];
__device__ float g_agg[NN * 24];
__device__ int   g_is64;   // 1 if edge_index is int64, 0 if int32

// ---------------------------------------------------------------------------
__global__ void k_init() {
    int i = blockIdx.x * blockDim.x + threadIdx.x;
    int stride = gridDim.x * blockDim.x;
    for (int j = i; j < NN; j += stride) g_deg[j] = 0.0f;
    for (int j = i; j < NN * 24; j += stride) g_agg[j] = 0.0f;
}

// Detect edge_index element width (int64 high words are all zero).
__global__ void k_probe(const int* __restrict__ ei32) {
    int nz = 0;
    for (int j = threadIdx.x; j < 1024; j += blockDim.x)
        if (ei32[2 * j + 1] != 0) nz = 1;
    int any = __syncthreads_or(nz);
    if (threadIdx.x == 0) g_is64 = any ? 0 : 1;
}

__device__ __forceinline__ void load_edge(const int* ei32, int e, int& s, int& d) {
    if (g_is64) { s = ei32[2 * e]; d = ei32[2 * (NE + e)]; }
    else        { s = ei32[e];     d = ei32[NE + e]; }
}

__global__ void k_deg(const int* __restrict__ ei32) {
    int e = blockIdx.x * blockDim.x + threadIdx.x;
    if (e >= NE) return;
    int s, d;
    load_edge(ei32, e, s, d);
    atomicAdd(&g_deg[d], 1.0f);
}

__global__ void k_dinv() {
    int n = blockIdx.x * blockDim.x + threadIdx.x;
    if (n < NN) g_dinv[n] = rsqrtf(g_deg[n] + 1.0f);
}

// g_agg[dst][t][c] += dinv[src]*dinv[dst] * x[src][t][c]  (all 24 at once)
__global__ void k_scatter(const int* __restrict__ ei32,
                          const float* __restrict__ x) {
    int e = blockIdx.x * blockDim.x + threadIdx.x;
    if (e >= NE) return;
    int s, d;
    load_edge(ei32, e, s, d);
    float w = g_dinv[s] * g_dinv[d];
    const float4* xs = (const float4*)(x + (size_t)s * 24);
    float* ag = g_agg + (size_t)d * 24;
#pragma unroll
    for (int q = 0; q < 6; q++) {
        float4 v = xs[q];
        atomicAdd(&ag[4 * q + 0], w * v.x);
        atomicAdd(&ag[4 * q + 1], w * v.y);
        atomicAdd(&ag[4 * q + 2], w * v.z);
        atomicAdd(&ag[4 * q + 3], w * v.w);
    }
}

// ---------------------------------------------------------------------------
// Packed f32x2 helpers (FFMA2: 2 fp32 FMAs per fma-pipe issue slot)
__device__ __forceinline__ unsigned long long pk2(float v) {
    unsigned long long r;
    asm("mov.b64 %0, {%1, %1};" : "=l"(r) : "f"(v));
    return r;
}
__device__ __forceinline__ void fma2(unsigned long long& acc,
                                     unsigned long long a,
                                     unsigned long long b) {
    asm("fma.rn.f32x2 %0, %1, %2, %0;" : "+l"(acc) : "l"(a), "l"(b));
}
__device__ __forceinline__ void unpk2(float& lo, float& hi, unsigned long long v) {
    asm("mov.b64 {%0, %1}, %2;" : "=f"(lo), "=f"(hi) : "l"(v));
}

// Fused: GCN projection (2->64) + 12-step GRU + FC readout, per 64-node tile.
// 256 threads = 4 node-groups (16 nodes) x 64 gate-columns. h lives in SMEM.
__global__ void __launch_bounds__(256, 1)
k_fused(const float* __restrict__ x,
        const float* __restrict__ W_gcn, const float* __restrict__ b_gcn,
        const float* __restrict__ W_ih,  const float* __restrict__ W_hh,
        const float* __restrict__ b_ih,  const float* __restrict__ b_hh,
        const float* __restrict__ W_fc,  const float* __restrict__ b_fc,
        float* __restrict__ out) {
    extern __shared__ float sm[];
    float* sWih = sm;                 // [64][192] k-major (transposed)
    float* sWhh = sWih + 64 * 192;    // [64][192]
    float* sBih = sWhh + 64 * 192;    // 192
    float* sBhh = sBih + 192;         // 192
    float* sWg  = sBhh + 192;         // [2][64]
    float* sBg  = sWg + 128;          // 64
    float* sWfc = sBg + 64;           // 64
    float* sXA  = sWfc + 64;          // [NPB][24]
    float* sS   = sXA + NPB * 24;     // [64][SROW] spatial (k-major)
    float* sH   = sS + 64 * SROW;     // [64][SROW] hidden  (k-major)

    int tid = threadIdx.x;
    int node0 = blockIdx.x * NPB;

    for (int i = tid; i < 192 * 64; i += 256) {
        int g = i >> 6, k = i & 63;
        sWih[k * 192 + g] = W_ih[i];
        sWhh[k * 192 + g] = W_hh[i];
    }
    for (int i = tid; i < 192; i += 256) { sBih[i] = b_ih[i]; sBhh[i] = b_hh[i]; }
    for (int i = tid; i < 128; i += 256) sWg[i] = W_gcn[i];
    if (tid < 64) { sBg[tid] = b_gcn[tid]; sWfc[tid] = W_fc[tid]; }

    for (int i = tid; i < NPB * 24; i += 256) {
        int n = i / 24, c = i - n * 24;
        int node = node0 + n;
        float v = 0.0f;
        if (node < NN) {
            float dv = g_dinv[node];
            v = g_agg[(size_t)node * 24 + c] + dv * dv * x[(size_t)node * 24 + c];
        }
        sXA[i] = v;
    }
    for (int i = tid; i < 64 * SROW; i += 256) sH[i] = 0.0f;
    __syncthreads();

    int tx = tid & 63;   // gate column j
    int ty = tid >> 6;   // node-group
    int nb = ty * 16;

    float br  = sBih[tx]       + sBhh[tx];
    float bz  = sBih[64 + tx]  + sBhh[64 + tx];
    float bin = sBih[128 + tx];
    float bhn = sBhh[128 + tx];
    float wg0 = sWg[tx], wg1 = sWg[64 + tx], bg = sBg[tx];

    unsigned long long br2  = pk2(br),  bz2  = pk2(bz);
    unsigned long long bin2 = pk2(bin), bhn2 = pk2(bhn);

    // spatial for t=0
#pragma unroll
    for (int i = 0; i < 16; i++) {
        int n = nb + i;
        float v = fmaf(sXA[n * 24], wg0, fmaf(sXA[n * 24 + 1], wg1, bg));
        sS[tx * SROW + n] = fmaxf(v, 0.0f);
    }
    __syncthreads();

    for (int t = 0; t < TT; t++) {
        unsigned long long ar2[8], az2[8], ain2[8], ahn2[8];
#pragma unroll
        for (int p = 0; p < 8; p++) {
            ar2[p] = br2; az2[p] = bz2; ain2[p] = bin2; ahn2[p] = bhn2;
        }

        // fused GEMMs: gi = s @ Wih^T (r,z,n), gh = h @ Whh^T (r,z,n), packed x2
#pragma unroll 2
        for (int k = 0; k < 64; k++) {
            const float* wik = &sWih[k * 192 + tx];
            const float* whk = &sWhh[k * 192 + tx];
            unsigned long long wr2 = pk2(wik[0]);
            unsigned long long wz2 = pk2(wik[64]);
            unsigned long long wn2 = pk2(wik[128]);
            unsigned long long vr2 = pk2(whk[0]);
            unsigned long long vz2 = pk2(whk[64]);
            unsigned long long vn2 = pk2(whk[128]);
            const ulonglong2* sp = (const ulonglong2*)&sS[k * SROW + nb];
            const ulonglong2* hp = (const ulonglong2*)&sH[k * SROW + nb];
#pragma unroll
            for (int q = 0; q < 4; q++) {
                ulonglong2 sv = sp[q];
                ulonglong2 hv = hp[q];
                fma2(ar2 [2*q],   sv.x, wr2);  fma2(ar2 [2*q+1], sv.y, wr2);
                fma2(az2 [2*q],   sv.x, wz2);  fma2(az2 [2*q+1], sv.y, wz2);
                fma2(ain2[2*q],   sv.x, wn2);  fma2(ain2[2*q+1], sv.y, wn2);
                fma2(ar2 [2*q],   hv.x, vr2);  fma2(ar2 [2*q+1], hv.y, vr2);
                fma2(az2 [2*q],   hv.x, vz2);  fma2(az2 [2*q+1], hv.y, vz2);
                fma2(ahn2[2*q],   hv.x, vn2);  fma2(ahn2[2*q+1], hv.y, vn2);
            }
        }
        __syncthreads();  // all GEMM reads of sS/sH complete

        // gates + hidden update + spatial for t+1
#pragma unroll
        for (int p = 0; p < 8; p++) {
            float arL, arH, azL, azH, ainL, ainH, ahnL, ahnH;
            unpk2(arL,  arH,  ar2[p]);
            unpk2(azL,  azH,  az2[p]);
            unpk2(ainL, ainH, ain2[p]);
            unpk2(ahnL, ahnH, ahn2[p]);
            int n0 = nb + 2 * p;

            float r0 = 1.0f / (1.0f + __expf(-arL));
            float z0 = 1.0f / (1.0f + __expf(-azL));
            float n0v = tanhf(fmaf(r0, ahnL, ainL));
            float h0 = sH[tx * SROW + n0];
            sH[tx * SROW + n0] = fmaf(z0, h0 - n0v, n0v);

            float r1 = 1.0f / (1.0f + __expf(-arH));
            float z1 = 1.0f / (1.0f + __expf(-azH));
            float n1v = tanhf(fmaf(r1, ahnH, ainH));
            float h1 = sH[tx * SROW + n0 + 1];
            sH[tx * SROW + n0 + 1] = fmaf(z1, h1 - n1v, n1v);
        }
        if (t + 1 < TT) {
#pragma unroll
            for (int i = 0; i < 16; i++) {
                int n = nb + i;
                float v = fmaf(sXA[n * 24 + 2 * (t + 1)], wg0,
                          fmaf(sXA[n * 24 + 2 * (t + 1) + 1], wg1, bg));
                sS[tx * SROW + n] = fmaxf(v, 0.0f);
            }
        }
        __syncthreads();
    }

    // FC readout
    if (tid < NPB) {
        int node = node0 + tid;
        if (node < NN) {
            float acc = b_fc[0];
#pragma unroll
            for (int j = 0; j < 64; j++)
                acc = fmaf(sH[j * SROW + tid], sWfc[j], acc);
            out[node] = acc;
        }
    }
}

// ---------------------------------------------------------------------------
extern "C" void kernel_launch(void* const* d_in, const int* in_sizes, int n_in,
                              void* d_out, int out_size) {
    const float* x     = (const float*)d_in[0];
    const int*   ei32  = (const int*)d_in[1];   // int32 OR int64 (device-probed)
    const float* W_gcn = (const float*)d_in[2];
    const float* b_gcn = (const float*)d_in[3];
    const float* W_ih  = (const float*)d_in[4];
    const float* W_hh  = (const float*)d_in[5];
    const float* b_ih  = (const float*)d_in[6];
    const float* b_hh  = (const float*)d_in[7];
    const float* W_fc  = (const float*)d_in[8];
    const float* b_fc  = (const float*)d_in[9];
    float* out = (float*)d_out;

    const int smem_bytes =
        (2 * 64 * 192 + 2 * 192 + 128 + 64 + 64 + NPB * 24 + 2 * 64 * SROW) * 4;

    static bool attr_set = false;
    if (!attr_set) {
        cudaFuncSetAttribute(k_fused, cudaFuncAttributeMaxDynamicSharedMemorySize,
                             smem_bytes);
        attr_set = true;
    }

    k_init<<<256, 256>>>();
    k_probe<<<1, 256>>>(ei32);
    k_deg<<<(NE + 255) / 256, 256>>>(ei32);
    k_dinv<<<(NN + 255) / 256, 256>>>();
    k_scatter<<<(NE + 255) / 256, 256>>>(ei32, x);
    k_fused<<<(NN + NPB - 1) / NPB, 256, smem_bytes>>>(
        x, W_gcn, b_gcn, W_ih, W_hh, b_ih, b_hh, W_fc, b_fc, out);
}

// round 7
// speedup vs baseline: 2.0695x; 2.0328x over previous
#include <cuda_runtime.h>
#include <cuda_bf16.h>
#include <cstdint>
#include <math.h>

#define NN 50000
#define NE 800000
#define TT 12
#define NPB 128

// ---------------- device scratch (no allocations) ----------------
__device__ float g_deg[NN];
__device__ float g_agg[NN * 24];
__device__ int   g_is64;

// ---------------- preprocessing ----------------
__global__ void k_initprobe(const int* __restrict__ ei32) {
    int i = blockIdx.x * blockDim.x + threadIdx.x;
    int stride = gridDim.x * blockDim.x;
    for (int j = i; j < NN; j += stride) g_deg[j] = 0.0f;
    for (int j = i; j < NN * 24; j += stride) g_agg[j] = 0.0f;
    if (blockIdx.x == 0) {
        int nz = 0;
        for (int j = threadIdx.x; j < 1024; j += blockDim.x)
            if (ei32[2 * j + 1] != 0) nz = 1;
        int any = __syncthreads_or(nz);
        if (threadIdx.x == 0) g_is64 = any ? 0 : 1;
    }
}

__device__ __forceinline__ void load_edge(const int* ei32, int e, int& s, int& d) {
    if (g_is64) { s = ei32[2 * e]; d = ei32[2 * (NE + e)]; }
    else        { s = ei32[e];     d = ei32[NE + e]; }
}

__global__ void k_deg(const int* __restrict__ ei32) {
    int e = blockIdx.x * blockDim.x + threadIdx.x;
    if (e >= NE) return;
    int s, d;
    load_edge(ei32, e, s, d);
    atomicAdd(&g_deg[d], 1.0f);
}

__global__ void k_scatter(const int* __restrict__ ei32, const float* __restrict__ x) {
    int e = blockIdx.x * blockDim.x + threadIdx.x;
    if (e >= NE) return;
    int s, d;
    load_edge(ei32, e, s, d);
    float w = rsqrtf(g_deg[s] + 1.0f) * rsqrtf(g_deg[d] + 1.0f);
    const float4* xs = (const float4*)(x + (size_t)s * 24);
    float* ag = g_agg + (size_t)d * 24;
#pragma unroll
    for (int q = 0; q < 6; q++) {
        float4 v = xs[q];
        atomicAdd(&ag[4 * q + 0], w * v.x);
        atomicAdd(&ag[4 * q + 1], w * v.y);
        atomicAdd(&ag[4 * q + 2], w * v.z);
        atomicAdd(&ag[4 * q + 3], w * v.w);
    }
}

// ---------------- bf16 helpers ----------------
__device__ __forceinline__ float fhi(float x) {
    return __bfloat162float(__float2bfloat16_rn(x));
}
__device__ __forceinline__ uint32_t pk(float a, float b) {  // low=a, high=b
    __nv_bfloat162 t = __floats2bfloat162_rn(a, b);
    return *reinterpret_cast<uint32_t*>(&t);
}

// m16n8k16 row.col bf16 MMA, fp32 accumulate (plain PTX — no arch suffix needed)
__device__ __forceinline__ void mma16816(float* d, uint32_t a0, uint32_t a1,
                                         uint32_t a2, uint32_t a3,
                                         uint32_t b0, uint32_t b1) {
    asm volatile(
        "mma.sync.aligned.m16n8k16.row.col.f32.bf16.bf16.f32 "
        "{%0,%1,%2,%3}, {%4,%5,%6,%7}, {%8,%9}, {%0,%1,%2,%3};"
        : "+f"(d[0]), "+f"(d[1]), "+f"(d[2]), "+f"(d[3])
        : "r"(a0), "r"(a1), "r"(a2), "r"(a3), "r"(b0), "r"(b1));
}

// ---------------- smem layout (bytes) ----------------
#define SM_B1    0          // 128 frags x 32 lanes x 16B = 64KB  (rz: K=128,N=128)
#define SM_B2    65536      // 32 frags  x 512B = 16KB            (Wih_n: K=64,N=64)
#define SM_B3    81920      // 16KB                               (Whh_n)
#define SM_XA    98304      // float2[12][128] = 12KB
#define SM_WG3   110592     // float4[64] = 1KB : {wg0, wg1, bg, 0}
#define SM_BIAS  111616     // float4[64] = 1KB : {br, bz, bin, bhn}
#define SM_WFC   112640     // float[64]
#define SM_TOTAL 112896

__global__ void __launch_bounds__(256)
k_fused(const float* __restrict__ x,
        const float* __restrict__ W_gcn, const float* __restrict__ b_gcn,
        const float* __restrict__ W_ih,  const float* __restrict__ W_hh,
        const float* __restrict__ b_ih,  const float* __restrict__ b_hh,
        const float* __restrict__ W_fc,  const float* __restrict__ b_fc,
        float* __restrict__ out) {
    extern __shared__ char smem[];
    const int tid  = threadIdx.x;
    const int wid  = tid >> 5;
    const int lane = tid & 31;
    const int gid  = lane >> 2;   // row group 0..7
    const int tig  = lane & 3;    // thread-in-group
    const int node0 = blockIdx.x * NPB;
    const int n0 = wid * 16 + gid;      // local node row (thread's row 0)
    const int n1 = n0 + 8;              // thread's row 1

    // ---- build B fragments (hi/lo interleaved, fragment-major) ----
    // item layout: frag f, lane l -> uint4 {bh0, bh1, bl0, bl1}
    for (int i = tid; i < 6144; i += 256) {
        int f, l;
        const float* Wrow;
        int k0;
        uint32_t dst;
        if (i < 4096) {                       // B1: rz, 8kt x 16nt
            f = i >> 5; l = i & 31;
            int kt = f >> 4, nt = f & 15;
            int g = l >> 2, tg = l & 3;
            int j = 8 * nt + g;
            k0 = 16 * kt + 2 * tg;
            Wrow = (kt < 4) ? (W_ih + j * 64 + k0) : (W_hh + j * 64 + (k0 - 64));
            dst = SM_B1 + (uint32_t)(f * 32 + l) * 16;
        } else if (i < 5120) {                // B2: Wih_n, 4kt x 8nt
            int ii = i - 4096;
            f = ii >> 5; l = ii & 31;
            int kt = f >> 3, nt = f & 7;
            int g = l >> 2, tg = l & 3;
            int j = 8 * nt + g;
            k0 = 16 * kt + 2 * tg;
            Wrow = W_ih + (128 + j) * 64 + k0;
            dst = SM_B2 + (uint32_t)(f * 32 + l) * 16;
        } else {                              // B3: Whh_n
            int ii = i - 5120;
            f = ii >> 5; l = ii & 31;
            int kt = f >> 3, nt = f & 7;
            int g = l >> 2, tg = l & 3;
            int j = 8 * nt + g;
            k0 = 16 * kt + 2 * tg;
            Wrow = W_hh + (128 + j) * 64 + k0;
            dst = SM_B3 + (uint32_t)(f * 32 + l) * 16;
        }
        float w0 = Wrow[0], w1 = Wrow[1], w8 = Wrow[8], w9 = Wrow[9];
        float h0 = fhi(w0), h1 = fhi(w1), h8 = fhi(w8), h9 = fhi(w9);
        uint4 v;
        v.x = pk(h0, h1);
        v.y = pk(h8, h9);
        v.z = pk(w0 - h0, w1 - h1);
        v.w = pk(w8 - h8, w9 - h9);
        *(uint4*)(smem + dst) = v;
    }

    // ---- XA: agg + selfnorm*x, layout float2[t][n] ----
    float* sXA = (float*)(smem + SM_XA);
    for (int i = tid; i < NPB * 24; i += 256) {
        int n = i / 24, cc = i - n * 24;
        int t = cc >> 1, c = cc & 1;
        int node = node0 + n;
        float v = 0.0f;
        if (node < NN) {
            float dv = rsqrtf(g_deg[node] + 1.0f);
            v = g_agg[(size_t)node * 24 + cc] + dv * dv * x[(size_t)node * 24 + cc];
        }
        sXA[(t * 128 + n) * 2 + c] = v;
    }
    if (tid < 64) {
        float4* wg3 = (float4*)(smem + SM_WG3);
        wg3[tid] = make_float4(W_gcn[tid], W_gcn[64 + tid], b_gcn[tid], 0.0f);
        float4* bia = (float4*)(smem + SM_BIAS);
        bia[tid] = make_float4(b_ih[tid] + b_hh[tid],
                               b_ih[64 + tid] + b_hh[64 + tid],
                               b_ih[128 + tid], b_hh[128 + tid]);
        ((float*)(smem + SM_WFC))[tid] = W_fc[tid];
    }
    __syncthreads();

    const float4* sWG3  = (const float4*)(smem + SM_WG3);
    const float4* sBIAS = (const float4*)(smem + SM_BIAS);
    const float*  sWFC  = (const float*)(smem + SM_WFC);

    // ---- hidden state in registers, D-fragment layout per nt (j-tile) ----
    float h[8][4];
#pragma unroll
    for (int nt = 0; nt < 8; nt++)
#pragma unroll
        for (int q = 0; q < 4; q++) h[nt][q] = 0.0f;

#pragma unroll 1
    for (int t = 0; t < TT; t++) {
        // xa for this thread's two node rows
        float2 xaA = *(const float2*)(sXA + (t * 128 + n0) * 2);
        float2 xaB = *(const float2*)(sXA + (t * 128 + n1) * 2);

        // ---- S fragments (A, K=0..63), hi/lo ----
        uint32_t sfH[4][4], sfL[4][4];
#pragma unroll
        for (int kt = 0; kt < 4; kt++) {
            int k0 = 16 * kt + 2 * tig;
            float4 g0 = sWG3[k0], g1 = sWG3[k0 + 1];
            float4 g8 = sWG3[k0 + 8], g9 = sWG3[k0 + 9];
            float s00 = fmaxf(fmaf(xaA.x, g0.x, fmaf(xaA.y, g0.y, g0.z)), 0.0f);
            float s01 = fmaxf(fmaf(xaA.x, g1.x, fmaf(xaA.y, g1.y, g1.z)), 0.0f);
            float s10 = fmaxf(fmaf(xaB.x, g0.x, fmaf(xaB.y, g0.y, g0.z)), 0.0f);
            float s11 = fmaxf(fmaf(xaB.x, g1.x, fmaf(xaB.y, g1.y, g1.z)), 0.0f);
            float s08 = fmaxf(fmaf(xaA.x, g8.x, fmaf(xaA.y, g8.y, g8.z)), 0.0f);
            float s09 = fmaxf(fmaf(xaA.x, g9.x, fmaf(xaA.y, g9.y, g9.z)), 0.0f);
            float s18 = fmaxf(fmaf(xaB.x, g8.x, fmaf(xaB.y, g8.y, g8.z)), 0.0f);
            float s19 = fmaxf(fmaf(xaB.x, g9.x, fmaf(xaB.y, g9.y, g9.z)), 0.0f);
            float h00 = fhi(s00), h01 = fhi(s01), h10 = fhi(s10), h11 = fhi(s11);
            float h08 = fhi(s08), h09 = fhi(s09), h18 = fhi(s18), h19 = fhi(s19);
            sfH[kt][0] = pk(h00, h01); sfH[kt][1] = pk(h10, h11);
            sfH[kt][2] = pk(h08, h09); sfH[kt][3] = pk(h18, h19);
            sfL[kt][0] = pk(s00 - h00, s01 - h01);
            sfL[kt][1] = pk(s10 - h10, s11 - h11);
            sfL[kt][2] = pk(s08 - h08, s09 - h09);
            sfL[kt][3] = pk(s18 - h18, s19 - h19);
        }

        // ---- H fragments from register h (A layout == D layout) ----
        uint32_t hfH[4][4], hfL[4][4];
#pragma unroll
        for (int kt = 0; kt < 4; kt++) {
            int e0 = 2 * kt, e1 = 2 * kt + 1;
            float a = h[e0][0], b = h[e0][1], c = h[e0][2], d = h[e0][3];
            float e = h[e1][0], f = h[e1][1], g = h[e1][2], i2 = h[e1][3];
            float ha = fhi(a), hb = fhi(b), hc = fhi(c), hd = fhi(d);
            float he = fhi(e), hf = fhi(f), hg = fhi(g), hi2 = fhi(i2);
            hfH[kt][0] = pk(ha, hb);  hfH[kt][1] = pk(hc, hd);
            hfH[kt][2] = pk(he, hf);  hfH[kt][3] = pk(hg, hi2);
            hfL[kt][0] = pk(a - ha, b - hb);  hfL[kt][1] = pk(c - hc, d - hd);
            hfL[kt][2] = pk(e - he, f - hf);  hfL[kt][3] = pk(g - hg, i2 - hi2);
        }

        // ---- D_rz = [S|H] @ B1^T : 16 n-tiles (r: 0..7, z: 8..15), K=128 ----
        float accRZ[16][4];
#pragma unroll
        for (int nt = 0; nt < 16; nt++)
#pragma unroll
            for (int q = 0; q < 4; q++) accRZ[nt][q] = 0.0f;
#pragma unroll
        for (int nt = 0; nt < 16; nt++) {
#pragma unroll
            for (int kt = 0; kt < 8; kt++) {
                uint4 bv = *(const uint4*)(smem + SM_B1 +
                             (uint32_t)((kt * 16 + nt) * 32 + lane) * 16);
                const uint32_t* aH = (kt < 4) ? sfH[kt] : hfH[kt - 4];
                const uint32_t* aL = (kt < 4) ? sfL[kt] : hfL[kt - 4];
                mma16816(accRZ[nt], aH[0], aH[1], aH[2], aH[3], bv.x, bv.y);
                mma16816(accRZ[nt], aH[0], aH[1], aH[2], aH[3], bv.z, bv.w);
                mma16816(accRZ[nt], aL[0], aL[1], aL[2], aL[3], bv.x, bv.y);
            }
        }

        // ---- D_in = S @ Wih_n^T ; D_hn = H @ Whh_n^T (K=64, N=64) ----
        float accIn[8][4], accHn[8][4];
#pragma unroll
        for (int nt = 0; nt < 8; nt++)
#pragma unroll
            for (int q = 0; q < 4; q++) { accIn[nt][q] = 0.0f; accHn[nt][q] = 0.0f; }
#pragma unroll
        for (int nt = 0; nt < 8; nt++) {
#pragma unroll
            for (int kt = 0; kt < 4; kt++) {
                uint4 b2 = *(const uint4*)(smem + SM_B2 +
                             (uint32_t)((kt * 8 + nt) * 32 + lane) * 16);
                mma16816(accIn[nt], sfH[kt][0], sfH[kt][1], sfH[kt][2], sfH[kt][3], b2.x, b2.y);
                mma16816(accIn[nt], sfH[kt][0], sfH[kt][1], sfH[kt][2], sfH[kt][3], b2.z, b2.w);
                mma16816(accIn[nt], sfL[kt][0], sfL[kt][1], sfL[kt][2], sfL[kt][3], b2.x, b2.y);
                uint4 b3 = *(const uint4*)(smem + SM_B3 +
                             (uint32_t)((kt * 8 + nt) * 32 + lane) * 16);
                mma16816(accHn[nt], hfH[kt][0], hfH[kt][1], hfH[kt][2], hfH[kt][3], b3.x, b3.y);
                mma16816(accHn[nt], hfH[kt][0], hfH[kt][1], hfH[kt][2], hfH[kt][3], b3.z, b3.w);
                mma16816(accHn[nt], hfL[kt][0], hfL[kt][1], hfL[kt][2], hfL[kt][3], b3.x, b3.y);
            }
        }

        // ---- gates + hidden update ----
#pragma unroll
        for (int nt = 0; nt < 8; nt++) {
            int j0 = 8 * nt + 2 * tig;
            float4 bj0 = sBIAS[j0];
            float4 bj1 = sBIAS[j0 + 1];
#pragma unroll
            for (int q = 0; q < 4; q++) {
                float4 bb = (q & 1) ? bj1 : bj0;
                float r  = 1.0f / (1.0f + __expf(-(accRZ[nt][q] + bb.x)));
                float z  = 1.0f / (1.0f + __expf(-(accRZ[nt + 8][q] + bb.y)));
                float nn = tanhf(fmaf(r, accHn[nt][q] + bb.w, accIn[nt][q] + bb.z));
                h[nt][q] = fmaf(z, h[nt][q] - nn, nn);
            }
        }
    }

    // ---- FC readout: reduce over j within each lane-quad ----
    float pA = 0.0f, pB = 0.0f;
#pragma unroll
    for (int nt = 0; nt < 8; nt++) {
        int j0 = 8 * nt + 2 * tig;
        float w0 = sWFC[j0], w1 = sWFC[j0 + 1];
        pA = fmaf(h[nt][0], w0, fmaf(h[nt][1], w1, pA));
        pB = fmaf(h[nt][2], w0, fmaf(h[nt][3], w1, pB));
    }
    pA += __shfl_xor_sync(0xFFFFFFFF, pA, 1);
    pA += __shfl_xor_sync(0xFFFFFFFF, pA, 2);
    pB += __shfl_xor_sync(0xFFFFFFFF, pB, 1);
    pB += __shfl_xor_sync(0xFFFFFFFF, pB, 2);
    if (tig == 0) {
        float bfc = b_fc[0];
        int nodeA = node0 + n0;
        int nodeB = node0 + n1;
        if (nodeA < NN) out[nodeA] = pA + bfc;
        if (nodeB < NN) out[nodeB] = pB + bfc;
    }
}

// ---------------- launch ----------------
extern "C" void kernel_launch(void* const* d_in, const int* in_sizes, int n_in,
                              void* d_out, int out_size) {
    const float* x     = (const float*)d_in[0];
    const int*   ei32  = (const int*)d_in[1];   // int32 OR int64 (device-probed)
    const float* W_gcn = (const float*)d_in[2];
    const float* b_gcn = (const float*)d_in[3];
    const float* W_ih  = (const float*)d_in[4];
    const float* W_hh  = (const float*)d_in[5];
    const float* b_ih  = (const float*)d_in[6];
    const float* b_hh  = (const float*)d_in[7];
    const float* W_fc  = (const float*)d_in[8];
    const float* b_fc  = (const float*)d_in[9];
    float* out = (float*)d_out;

    static bool attr_set = false;
    if (!attr_set) {
        cudaFuncSetAttribute(k_fused, cudaFuncAttributeMaxDynamicSharedMemorySize,
                             SM_TOTAL);
        attr_set = true;
    }

    k_initprobe<<<256, 256>>>(ei32);
    k_deg<<<(NE + 255) / 256, 256>>>(ei32);
    k_scatter<<<(NE + 255) / 256, 256>>>(ei32, x);
    k_fused<<<(NN + NPB - 1) / NPB, 256, SM_TOTAL>>>(
        x, W_gcn, b_gcn, W_ih, W_hh, b_ih, b_hh, W_fc, b_fc, out);
}

// round 8
// speedup vs baseline: 2.3559x; 1.1384x over previous
#include <cuda_runtime.h>
#include <cuda_bf16.h>
#include <cstdint>
#include <math.h>

#define NN 50000
#define NE 800000
#define TT 12
#define NPB 128

// ---------------- device scratch (no allocations) ----------------
__device__ float g_deg[NN];
__device__ float g_agg[NN * 24];
__device__ int   g_is64;

// ---------------- preprocessing ----------------
__global__ void k_initprobe(const int* __restrict__ ei32) {
    int i = blockIdx.x * blockDim.x + threadIdx.x;
    int stride = gridDim.x * blockDim.x;
    for (int j = i; j < NN; j += stride) g_deg[j] = 0.0f;
    for (int j = i; j < NN * 24; j += stride) g_agg[j] = 0.0f;
    if (blockIdx.x == 0) {
        int nz = 0;
        for (int j = threadIdx.x; j < 1024; j += blockDim.x)
            if (ei32[2 * j + 1] != 0) nz = 1;
        int any = __syncthreads_or(nz);
        if (threadIdx.x == 0) g_is64 = any ? 0 : 1;
    }
}

__device__ __forceinline__ void load_edge(const int* ei32, int e, int& s, int& d) {
    if (g_is64) { s = ei32[2 * e]; d = ei32[2 * (NE + e)]; }
    else        { s = ei32[e];     d = ei32[NE + e]; }
}

__global__ void k_deg(const int* __restrict__ ei32) {
    int e = blockIdx.x * blockDim.x + threadIdx.x;
    if (e >= NE) return;
    int s, d;
    load_edge(ei32, e, s, d);
    atomicAdd(&g_deg[d], 1.0f);
}

__global__ void k_scatter(const int* __restrict__ ei32, const float* __restrict__ x) {
    int e = blockIdx.x * blockDim.x + threadIdx.x;
    if (e >= NE) return;
    int s, d;
    load_edge(ei32, e, s, d);
    float w = rsqrtf(g_deg[s] + 1.0f) * rsqrtf(g_deg[d] + 1.0f);
    const float4* xs = (const float4*)(x + (size_t)s * 24);
    float* ag = g_agg + (size_t)d * 24;
#pragma unroll
    for (int q = 0; q < 6; q++) {
        float4 v = xs[q];
        atomicAdd(&ag[4 * q + 0], w * v.x);
        atomicAdd(&ag[4 * q + 1], w * v.y);
        atomicAdd(&ag[4 * q + 2], w * v.z);
        atomicAdd(&ag[4 * q + 3], w * v.w);
    }
}

// ---------------- bf16 helpers ----------------
__device__ __forceinline__ float fhi(float x) {
    return __bfloat162float(__float2bfloat16_rn(x));
}
__device__ __forceinline__ uint32_t pk(float a, float b) {  // low=a, high=b
    __nv_bfloat162 t = __floats2bfloat162_rn(a, b);
    return *reinterpret_cast<uint32_t*>(&t);
}
__device__ __forceinline__ float2 upk(uint32_t u) {
    __nv_bfloat162 t = *reinterpret_cast<__nv_bfloat162*>(&u);
    return make_float2(__low2float(t), __high2float(t));
}

// m16n8k16 row.col bf16 MMA, fp32 accumulate (plain PTX, no arch suffix)
__device__ __forceinline__ void mma16816(float* d, const uint32_t* a,
                                         uint32_t b0, uint32_t b1) {
    asm volatile(
        "mma.sync.aligned.m16n8k16.row.col.f32.bf16.bf16.f32 "
        "{%0,%1,%2,%3}, {%4,%5,%6,%7}, {%8,%9}, {%0,%1,%2,%3};"
        : "+f"(d[0]), "+f"(d[1]), "+f"(d[2]), "+f"(d[3])
        : "r"(a[0]), "r"(a[1]), "r"(a[2]), "r"(a[3]), "r"(b0), "r"(b1));
}

// ---------------- smem layout (bytes) ----------------
#define SM_B1    0          // 128 frags x 32 lanes x 16B = 64KB  (rz: K=128,N=128)
#define SM_B2    65536      // 32 frags x 512B = 16KB             (Wih_n: K=64,N=64)
#define SM_B3    81920      // 16KB                               (Whh_n)
#define SM_XA    98304      // float2[12][128] = 12KB
#define SM_WG3   110592     // float4[64] : {wg0, wg1, bg, 0}
#define SM_BIAS  111616     // float4[64] : {br, bz, bin, bhn}
#define SM_WFC   112640     // float[64]
#define SM_TOTAL 112896     // <= 228KB/2 -> 2 CTAs per SM

__global__ void __launch_bounds__(256, 2)
k_fused(const float* __restrict__ x,
        const float* __restrict__ W_gcn, const float* __restrict__ b_gcn,
        const float* __restrict__ W_ih,  const float* __restrict__ W_hh,
        const float* __restrict__ b_ih,  const float* __restrict__ b_hh,
        const float* __restrict__ W_fc,  const float* __restrict__ b_fc,
        float* __restrict__ out) {
    extern __shared__ char smem[];
    const int tid  = threadIdx.x;
    const int wid  = tid >> 5;
    const int lane = tid & 31;
    const int gid  = lane >> 2;
    const int tig  = lane & 3;
    const int node0 = blockIdx.x * NPB;
    const int n0 = wid * 16 + gid;
    const int n1 = n0 + 8;

    // ---- build B fragments (hi/lo interleaved, fragment-major) ----
    for (int i = tid; i < 6144; i += 256) {
        int f, l;
        const float* Wrow;
        int k0;
        uint32_t dst;
        if (i < 4096) {                       // B1: rz, 8kt x 16nt
            f = i >> 5; l = i & 31;
            int kt = f >> 4, nt = f & 15;
            int g = l >> 2, tg = l & 3;
            int j = 8 * nt + g;
            k0 = 16 * kt + 2 * tg;
            Wrow = (kt < 4) ? (W_ih + j * 64 + k0) : (W_hh + j * 64 + (k0 - 64));
            dst = SM_B1 + (uint32_t)(f * 32 + l) * 16;
        } else if (i < 5120) {                // B2: Wih_n, 4kt x 8nt
            int ii = i - 4096;
            f = ii >> 5; l = ii & 31;
            int kt = f >> 3, nt = f & 7;
            int g = l >> 2, tg = l & 3;
            int j = 8 * nt + g;
            k0 = 16 * kt + 2 * tg;
            Wrow = W_ih + (128 + j) * 64 + k0;
            dst = SM_B2 + (uint32_t)(f * 32 + l) * 16;
        } else {                              // B3: Whh_n
            int ii = i - 5120;
            f = ii >> 5; l = ii & 31;
            int kt = f >> 3, nt = f & 7;
            int g = l >> 2, tg = l & 3;
            int j = 8 * nt + g;
            k0 = 16 * kt + 2 * tg;
            Wrow = W_hh + (128 + j) * 64 + k0;
            dst = SM_B3 + (uint32_t)(f * 32 + l) * 16;
        }
        float w0 = Wrow[0], w1 = Wrow[1], w8 = Wrow[8], w9 = Wrow[9];
        float h0 = fhi(w0), h1 = fhi(w1), h8 = fhi(w8), h9 = fhi(w9);
        uint4 v;
        v.x = pk(h0, h1);
        v.y = pk(h8, h9);
        v.z = pk(w0 - h0, w1 - h1);
        v.w = pk(w8 - h8, w9 - h9);
        *(uint4*)(smem + dst) = v;
    }

    // ---- XA: agg + selfnorm*x, layout float2[t][n] ----
    float* sXA = (float*)(smem + SM_XA);
    for (int i = tid; i < NPB * 24; i += 256) {
        int n = i / 24, cc = i - n * 24;
        int t = cc >> 1, c = cc & 1;
        int node = node0 + n;
        float v = 0.0f;
        if (node < NN) {
            float dv = rsqrtf(g_deg[node] + 1.0f);
            v = g_agg[(size_t)node * 24 + cc] + dv * dv * x[(size_t)node * 24 + cc];
        }
        sXA[(t * 128 + n) * 2 + c] = v;
    }
    if (tid < 64) {
        float4* wg3 = (float4*)(smem + SM_WG3);
        wg3[tid] = make_float4(W_gcn[tid], W_gcn[64 + tid], b_gcn[tid], 0.0f);
        float4* bia = (float4*)(smem + SM_BIAS);
        bia[tid] = make_float4(b_ih[tid] + b_hh[tid],
                               b_ih[64 + tid] + b_hh[64 + tid],
                               b_ih[128 + tid], b_hh[128 + tid]);
        ((float*)(smem + SM_WFC))[tid] = W_fc[tid];
    }
    __syncthreads();

    const float4* sWG3  = (const float4*)(smem + SM_WG3);
    const float4* sBIAS = (const float4*)(smem + SM_BIAS);
    const float*  sWFC  = (const float*)(smem + SM_WFC);

    // ---- hidden state kept PACKED as bf16 hi/lo A-fragments ----
    uint32_t hh[4][4], hl[4][4];
#pragma unroll
    for (int kt = 0; kt < 4; kt++)
#pragma unroll
        for (int q = 0; q < 4; q++) { hh[kt][q] = 0u; hl[kt][q] = 0u; }

#pragma unroll 1
    for (int t = 0; t < TT; t++) {
        float2 xaA = *(const float2*)(sXA + (t * 128 + n0) * 2);
        float2 xaB = *(const float2*)(sXA + (t * 128 + n1) * 2);

        // ---- S fragments (hi/lo) ----
        uint32_t sfH[4][4], sfL[4][4];
#pragma unroll
        for (int kt = 0; kt < 4; kt++) {
            int k0 = 16 * kt + 2 * tig;
            float4 g0 = sWG3[k0], g1 = sWG3[k0 + 1];
            float4 g8 = sWG3[k0 + 8], g9 = sWG3[k0 + 9];
            float s00 = fmaxf(fmaf(xaA.x, g0.x, fmaf(xaA.y, g0.y, g0.z)), 0.0f);
            float s01 = fmaxf(fmaf(xaA.x, g1.x, fmaf(xaA.y, g1.y, g1.z)), 0.0f);
            float s10 = fmaxf(fmaf(xaB.x, g0.x, fmaf(xaB.y, g0.y, g0.z)), 0.0f);
            float s11 = fmaxf(fmaf(xaB.x, g1.x, fmaf(xaB.y, g1.y, g1.z)), 0.0f);
            float s08 = fmaxf(fmaf(xaA.x, g8.x, fmaf(xaA.y, g8.y, g8.z)), 0.0f);
            float s09 = fmaxf(fmaf(xaA.x, g9.x, fmaf(xaA.y, g9.y, g9.z)), 0.0f);
            float s18 = fmaxf(fmaf(xaB.x, g8.x, fmaf(xaB.y, g8.y, g8.z)), 0.0f);
            float s19 = fmaxf(fmaf(xaB.x, g9.x, fmaf(xaB.y, g9.y, g9.z)), 0.0f);
            float h00 = fhi(s00), h01 = fhi(s01), h10 = fhi(s10), h11 = fhi(s11);
            float h08 = fhi(s08), h09 = fhi(s09), h18 = fhi(s18), h19 = fhi(s19);
            sfH[kt][0] = pk(h00, h01); sfH[kt][1] = pk(h10, h11);
            sfH[kt][2] = pk(h08, h09); sfH[kt][3] = pk(h18, h19);
            sfL[kt][0] = pk(s00 - h00, s01 - h01);
            sfL[kt][1] = pk(s10 - h10, s11 - h11);
            sfL[kt][2] = pk(s08 - h08, s09 - h09);
            sfL[kt][3] = pk(s18 - h18, s19 - h19);
        }

        // ---- per-nt: accumulate all 4 gate tiles, update h, repack ----
        uint32_t nhh[4][4], nhl[4][4];
#pragma unroll
        for (int nt = 0; nt < 8; nt++) {
            float aR[4] = {0, 0, 0, 0}, aZ[4] = {0, 0, 0, 0};
            float aI[4] = {0, 0, 0, 0}, aN[4] = {0, 0, 0, 0};
#pragma unroll
            for (int kt = 0; kt < 8; kt++) {
                const uint32_t* xH = (kt < 4) ? sfH[kt] : hh[kt - 4];
                const uint32_t* xL = (kt < 4) ? sfL[kt] : hl[kt - 4];
                uint4 bR = *(const uint4*)(smem + SM_B1 +
                             (uint32_t)((kt * 16 + nt) * 32 + lane) * 16);
                mma16816(aR, xH, bR.x, bR.y);
                mma16816(aR, xH, bR.z, bR.w);
                mma16816(aR, xL, bR.x, bR.y);
                uint4 bZ = *(const uint4*)(smem + SM_B1 +
                             (uint32_t)((kt * 16 + nt + 8) * 32 + lane) * 16);
                mma16816(aZ, xH, bZ.x, bZ.y);
                mma16816(aZ, xH, bZ.z, bZ.w);
                mma16816(aZ, xL, bZ.x, bZ.y);
                if (kt < 4) {
                    uint4 b2 = *(const uint4*)(smem + SM_B2 +
                                 (uint32_t)((kt * 8 + nt) * 32 + lane) * 16);
                    mma16816(aI, sfH[kt], b2.x, b2.y);
                    mma16816(aI, sfH[kt], b2.z, b2.w);
                    mma16816(aI, sfL[kt], b2.x, b2.y);
                    uint4 b3 = *(const uint4*)(smem + SM_B3 +
                                 (uint32_t)((kt * 8 + nt) * 32 + lane) * 16);
                    mma16816(aN, hh[kt], b3.x, b3.y);
                    mma16816(aN, hh[kt], b3.z, b3.w);
                    mma16816(aN, hl[kt], b3.x, b3.y);
                }
            }
            // gates: old h reconstructed from packed state
            int kt2 = nt >> 1, base = (nt & 1) * 2;
            float2 oh0H = upk(hh[kt2][base]),     oh0L = upk(hl[kt2][base]);
            float2 oh1H = upk(hh[kt2][base + 1]), oh1L = upk(hl[kt2][base + 1]);
            float hold[4] = { oh0H.x + oh0L.x, oh0H.y + oh0L.y,
                              oh1H.x + oh1L.x, oh1H.y + oh1L.y };
            int j0 = 8 * nt + 2 * tig;
            float4 bj0 = sBIAS[j0];
            float4 bj1 = sBIAS[j0 + 1];
            float hn[4];
#pragma unroll
            for (int q = 0; q < 4; q++) {
                float4 bb = (q & 1) ? bj1 : bj0;
                float r  = 1.0f / (1.0f + __expf(-(aR[q] + bb.x)));
                float z  = 1.0f / (1.0f + __expf(-(aZ[q] + bb.y)));
                float nn = tanhf(fmaf(r, aN[q] + bb.w, aI[q] + bb.z));
                hn[q] = fmaf(z, hold[q] - nn, nn);
            }
            float p0 = fhi(hn[0]), p1 = fhi(hn[1]);
            float p2 = fhi(hn[2]), p3 = fhi(hn[3]);
            nhh[kt2][base]     = pk(p0, p1);
            nhh[kt2][base + 1] = pk(p2, p3);
            nhl[kt2][base]     = pk(hn[0] - p0, hn[1] - p1);
            nhl[kt2][base + 1] = pk(hn[2] - p2, hn[3] - p3);
        }
#pragma unroll
        for (int kt = 0; kt < 4; kt++)
#pragma unroll
            for (int q = 0; q < 4; q++) { hh[kt][q] = nhh[kt][q]; hl[kt][q] = nhl[kt][q]; }
    }

    // ---- FC readout ----
    float pA = 0.0f, pB = 0.0f;
#pragma unroll
    for (int nt = 0; nt < 8; nt++) {
        int kt2 = nt >> 1, base = (nt & 1) * 2;
        float2 aHv = upk(hh[kt2][base]),     aLv = upk(hl[kt2][base]);
        float2 bHv = upk(hh[kt2][base + 1]), bLv = upk(hl[kt2][base + 1]);
        int j0 = 8 * nt + 2 * tig;
        float w0 = sWFC[j0], w1 = sWFC[j0 + 1];
        pA = fmaf(aHv.x + aLv.x, w0, fmaf(aHv.y + aLv.y, w1, pA));
        pB = fmaf(bHv.x + bLv.x, w0, fmaf(bHv.y + bLv.y, w1, pB));
    }
    pA += __shfl_xor_sync(0xFFFFFFFF, pA, 1);
    pA += __shfl_xor_sync(0xFFFFFFFF, pA, 2);
    pB += __shfl_xor_sync(0xFFFFFFFF, pB, 1);
    pB += __shfl_xor_sync(0xFFFFFFFF, pB, 2);
    if (tig == 0) {
        float bfc = b_fc[0];
        int nodeA = node0 + n0;
        int nodeB = node0 + n1;
        if (nodeA < NN) out[nodeA] = pA + bfc;
        if (nodeB < NN) out[nodeB] = pB + bfc;
    }
}

// ---------------- launch ----------------
extern "C" void kernel_launch(void* const* d_in, const int* in_sizes, int n_in,
                              void* d_out, int out_size) {
    const float* x     = (const float*)d_in[0];
    const int*   ei32  = (const int*)d_in[1];
    const float* W_gcn = (const float*)d_in[2];
    const float* b_gcn = (const float*)d_in[3];
    const float* W_ih  = (const float*)d_in[4];
    const float* W_hh  = (const float*)d_in[5];
    const float* b_ih  = (const float*)d_in[6];
    const float* b_hh  = (const float*)d_in[7];
    const float* W_fc  = (const float*)d_in[8];
    const float* b_fc  = (const float*)d_in[9];
    float* out = (float*)d_out;

    static bool attr_set = false;
    if (!attr_set) {
        cudaFuncSetAttribute(k_fused, cudaFuncAttributeMaxDynamicSharedMemorySize,
                             SM_TOTAL);
        attr_set = true;
    }

    k_initprobe<<<256, 256>>>(ei32);
    k_deg<<<(NE + 255) / 256, 256>>>(ei32);
    k_scatter<<<(NE + 255) / 256, 256>>>(ei32, x);
    k_fused<<<(NN + NPB - 1) / NPB, 256, SM_TOTAL>>>(
        x, W_gcn, b_gcn, W_ih, W_hh, b_ih, b_hh, W_fc, b_fc, out);
}